// round 14
// baseline (speedup 1.0000x reference)
#include <cuda_runtime.h>
#include <cuda_bf16.h>
#include <cuda_fp16.h>
#include <cstdint>

// Problem constants
#define BT      16384           // B*T = 32*512
#define HDIM    256
#define NCAT    8
#define NCONT   24
#define VPAD    513
#define ODIM    32
#define NEGINF  (-1e30f)
#define NPAD    576             // padded vocab cols for catWT

// Output layout (flattened tuple (u, o, c)):
#define OFF_O   (BT * ODIM)
#define OFF_C   (2 * BT * ODIM)

// Scratch (static __device__ arrays — no allocation allowed)
__device__ __align__(16) __half g_h1h[BT * HDIM];  // h1 split hi
__device__ __align__(16) __half g_h1l[BT * HDIM];  // h1 split lo
__device__ __align__(16) __half g_hh[BT * HDIM];   // h split hi (f16)
__device__ __align__(16) __half g_hl[BT * HDIM];   // h split lo (f16)
__device__ __align__(16) __half g_mwh[HDIM * HDIM]; // model_W^T hi [n][k]
__device__ __align__(16) __half g_mwl[HDIM * HDIM]; // model_W^T lo [n][k]
__device__ __align__(16) __half g_cwh[NCAT * NPAD * HDIM]; // cat_W^T hi [n][k]
__device__ __align__(16) __half g_cwl[NCAT * NPAD * HDIM]; // cat_W^T lo [n][k]
__device__ __align__(16) __half g_fwh[64 * HDIM];  // [fcu|fco]^T hi [j][k]
__device__ __align__(16) __half g_fwl[64 * HDIM];  // [fcu|fco]^T lo [j][k]
__device__ unsigned long long g_amax[NCAT * BT];   // packed (key<<32)|(1023-idx)

__constant__ int c_ncols[NCAT] = {513, 513, 257, 257, 129, 129, 65, 65};
// 30 FULL (f, n0) tiles of 64 valid cols (vocab+1 = k*64+1 for every f)
__constant__ signed char c_tf2[30] = {0,0,0,0,0,0,0,0, 1,1,1,1,1,1,1,1,
                                      2,2,2,2, 3,3,3,3, 4,4, 5,5, 6, 7};
__constant__ short c_tn2[30] = {0,64,128,192,256,320,384,448,
                                0,64,128,192,256,320,384,448,
                                0,64,128,192, 0,64,128,192,
                                0,64, 0,64, 0, 0};
__constant__ short c_colf[8] = {512,512,256,256,128,128,64,64};  // the "+1" col per f

// ---------------------------------------------------------------------------
// Warp-MMA helpers (baseline PTX, works on .target sm_100)
// ---------------------------------------------------------------------------
__device__ __forceinline__ uint32_t smem_u32(const void* p) {
    uint32_t a;
    asm("{ .reg .u64 t; cvta.to.shared.u64 t, %1; cvt.u32.u64 %0, t; }"
        : "=r"(a) : "l"(p));
    return a;
}

#define LDSM_X4(r0, r1, r2, r3, addr) \
    asm volatile("ldmatrix.sync.aligned.m8n8.x4.shared.b16 {%0,%1,%2,%3}, [%4];" \
        : "=r"(r0), "=r"(r1), "=r"(r2), "=r"(r3) : "r"(addr))

#define MMA16816(c0, c1, c2, c3, a0, a1, a2, a3, b0, b1) \
    asm volatile("mma.sync.aligned.m16n8k16.row.col.f32.f16.f16.f32 " \
        "{%0,%1,%2,%3}, {%4,%5,%6,%7}, {%8,%9}, {%0,%1,%2,%3};" \
        : "+f"(c0), "+f"(c1), "+f"(c2), "+f"(c3) \
        : "r"(a0), "r"(a1), "r"(a2), "r"(a3), "r"(b0), "r"(b1))

#define CP_A16(dst, srcp) \
    asm volatile("cp.async.cg.shared.global [%0], [%1], 16;" \
        :: "r"(dst), "l"(__cvta_generic_to_global(srcp)) : "memory")
#define CP_COMMIT() asm volatile("cp.async.commit_group;" ::: "memory")

// ---------------------------------------------------------------------------
// K_prep: cat_W [8,256,513] -> transposed padded f16 hi/lo [8,576,256]
// ---------------------------------------------------------------------------
__global__ void __launch_bounds__(256)
k_prep_catw(const float* __restrict__ catW) {
    __shared__ float tile[32][65];
    int bt = blockIdx.x;
    int f  = blockIdx.y;
    int k0 = (bt % 8) * 32;
    int n0 = (bt / 8) * 64;
    int tid = threadIdx.x;

    int n_local = tid & 63;
    int k_local = tid >> 6;              // 0..3
#pragma unroll
    for (int p = 0; p < 8; p++) {
        int k = k_local + p * 4;
        int n = n0 + n_local;
        tile[k][n_local] = (n < VPAD)
            ? catW[((size_t)f * HDIM + k0 + k) * VPAD + n] : 0.f;
    }
    __syncthreads();

    int k2 = tid & 31;
    int nl = tid >> 5;                   // 0..7
#pragma unroll
    for (int p = 0; p < 8; p++) {
        int n = nl + p * 8;
        float v = tile[k2][n];
        __half hi = __float2half_rn(v);
        __half lo = __float2half_rn(v - __half2float(hi));
        size_t o = ((size_t)f * NPAD + n0 + n) * HDIM + k0 + k2;
        g_cwh[o] = hi;
        g_cwl[o] = lo;
    }
}

// K_prep2: merged small preps — model_W^T (blocks 0..255) and [fcu|fco]^T
__global__ void k_prep_small(const float* __restrict__ Wm,
                             const float* __restrict__ fcuW,
                             const float* __restrict__ fcoW) {
    int b = blockIdx.x, k = threadIdx.x;
    if (b < HDIM) {
        float v = Wm[k * HDIM + b];
        __half hi = __float2half_rn(v);
        __half lo = __float2half_rn(v - __half2float(hi));
        g_mwh[b * HDIM + k] = hi;
        g_mwl[b * HDIM + k] = lo;
    } else {
        int j = b - HDIM;
        float v = (j < 32) ? fcuW[k * ODIM + j] : fcoW[k * ODIM + (j - 32)];
        __half hi = __float2half_rn(v);
        __half lo = __float2half_rn(v - __half2float(hi));
        g_fwh[j * HDIM + k] = hi;
        g_fwl[j * HDIM + k] = lo;
    }
}

// ---------------------------------------------------------------------------
// K1: h1 = mean(embs gather) + x_cont @ feat_W + feat_b -> split f16 hi/lo
// ---------------------------------------------------------------------------
__global__ void __launch_bounds__(256)
k_embed(const float* __restrict__ x,
        const float* __restrict__ embs,
        const float* __restrict__ feat_W,
        const float* __restrict__ feat_b) {
    int c   = threadIdx.x;
    int bt0 = blockIdx.x * 4;
    __shared__ float sx[4][32];
    if (c < 128) {
        int t = c >> 5, j = c & 31;
        sx[t][j] = x[(bt0 + t) * 32 + j];
    }
    __syncthreads();

    float fw[NCONT];
#pragma unroll
    for (int j = 0; j < NCONT; j++) fw[j] = feat_W[j * HDIM + c];
    float fb = feat_b[c];

#pragma unroll
    for (int t = 0; t < 4; t++) {
        float e = 0.f;
#pragma unroll
        for (int f = 0; f < NCAT; f++) {
            int id = (int)sx[t][f] + 1;
            e += embs[((size_t)f * VPAD + id) * HDIM + c];
        }
        float acc = fb + e * 0.125f;
#pragma unroll
        for (int j = 0; j < NCONT; j++)
            acc += sx[t][NCAT + j] * fw[j];
        __half hi = __float2half_rn(acc);
        __half lo = __float2half_rn(acc - __half2float(hi));
        g_h1h[(size_t)(bt0 + t) * HDIM + c] = hi;
        g_h1l[(size_t)(bt0 + t) * HDIM + c] = lo;
    }
}

// ---------------------------------------------------------------------------
// Double-buffered smem layout, K-chunk = 32 halves, pitch 40 (conflict-free:
// row addrs mod 128 = {0,80,32,112,64,16,96,48}).
// Per buffer: AH 0..10239, AL 10240..20479, BH 20480..25599, BL 25600..30719
// ---------------------------------------------------------------------------
#define KPITCH 40
#define BUF_SZ 30720
#define O_AL   10240
#define O_BH   20480
#define O_BL   25600
#define S_CAT2 (2 * BUF_SZ)             // 61440
#define SMEM_DB (S_CAT2 + 256)          // 61696
// stage (float[128][65] = 33280 B) reuses buffers after the MMA loop

// ---------------------------------------------------------------------------
// HMMA core 128x64, cp.async double-buffered, 8 chunks of K=32 (256 threads)
// ---------------------------------------------------------------------------
__device__ __forceinline__ void hmma_tile_db(
    uint32_t sbase, int tid, int wid, int lane,
    const __half* __restrict__ Ah, const __half* __restrict__ Al, int m0,
    const __half* __restrict__ Bh0, const __half* __restrict__ Bl0,
    float acc[2][4][4])
{
    const int rw = (wid & 3) * 32;
    const int cw = (wid >> 2) * 32;
    uint32_t a_row = (uint32_t)(lane & 15);
    uint32_t a_c8  = (uint32_t)((lane >> 4) * 8);
    uint32_t b_row = (uint32_t)((lane & 7) + ((lane >> 3) & 1) * 8);
    uint32_t b_c8  = (uint32_t)((lane >> 4) * 8);

    auto issue = [&](int buf, int kc) {
        uint32_t base = sbase + buf * BUF_SZ;
        // A: 128 rows x 32 halves, hi+lo: 512 x 16B each, 2/thread each
#pragma unroll
        for (int i = 0; i < 2; i++) {
            int id = tid + i * 256;
            int r  = id >> 2;
            int c8 = (id & 3) * 8;
            size_t src = (size_t)(m0 + r) * HDIM + kc + c8;
            uint32_t off = (uint32_t)((r * KPITCH + c8) * 2);
            CP_A16(base + off,        Ah + src);
            CP_A16(base + O_AL + off, Al + src);
        }
        // B: 64 rows x 32 halves, hi+lo: 256 x 16B each, 1/thread each
        {
            int r  = tid >> 2;
            int c8 = (tid & 3) * 8;
            size_t src = (size_t)r * HDIM + kc + c8;
            uint32_t off = (uint32_t)((r * KPITCH + c8) * 2);
            CP_A16(base + O_BH + off, Bh0 + src);
            CP_A16(base + O_BL + off, Bl0 + src);
        }
        CP_COMMIT();
    };

    issue(0, 0);
    int cur = 0;
#pragma unroll
    for (int ki = 0; ki < 8; ki++) {
        if (ki < 7) {
            issue(cur ^ 1, (ki + 1) * 32);
            asm volatile("cp.async.wait_group 1;" ::: "memory");
        } else {
            asm volatile("cp.async.wait_group 0;" ::: "memory");
        }
        __syncthreads();

        uint32_t bA  = sbase + cur * BUF_SZ;
        uint32_t bAl = bA + O_AL;
        uint32_t bBh = bA + O_BH;
        uint32_t bBl = bA + O_BL;
#pragma unroll
        for (int ks = 0; ks < 2; ks++) {
            int kk = ks * 16;
            uint32_t ah[2][4], al[2][4];
#pragma unroll
            for (int mf = 0; mf < 2; mf++) {
                uint32_t off = ((rw + mf * 16 + a_row) * KPITCH + kk + a_c8) * 2;
                LDSM_X4(ah[mf][0], ah[mf][1], ah[mf][2], ah[mf][3], bA  + off);
                LDSM_X4(al[mf][0], al[mf][1], al[mf][2], al[mf][3], bAl + off);
            }
            uint32_t bh[4][2], bl[4][2];
#pragma unroll
            for (int g = 0; g < 2; g++) {
                uint32_t off = ((cw + g * 16 + b_row) * KPITCH + kk + b_c8) * 2;
                uint32_t r0, r1, r2, r3;
                LDSM_X4(r0, r1, r2, r3, bBh + off);
                bh[g * 2 + 0][0] = r0; bh[g * 2 + 0][1] = r2;
                bh[g * 2 + 1][0] = r1; bh[g * 2 + 1][1] = r3;
                LDSM_X4(r0, r1, r2, r3, bBl + off);
                bl[g * 2 + 0][0] = r0; bl[g * 2 + 0][1] = r2;
                bl[g * 2 + 1][0] = r1; bl[g * 2 + 1][1] = r3;
            }
#pragma unroll
            for (int mf = 0; mf < 2; mf++)
#pragma unroll
                for (int nf = 0; nf < 4; nf++) {
                    MMA16816(acc[mf][nf][0], acc[mf][nf][1], acc[mf][nf][2], acc[mf][nf][3],
                             ah[mf][0], ah[mf][1], ah[mf][2], ah[mf][3],
                             bh[nf][0], bh[nf][1]);
                    MMA16816(acc[mf][nf][0], acc[mf][nf][1], acc[mf][nf][2], acc[mf][nf][3],
                             ah[mf][0], ah[mf][1], ah[mf][2], ah[mf][3],
                             bl[nf][0], bl[nf][1]);
                    MMA16816(acc[mf][nf][0], acc[mf][nf][1], acc[mf][nf][2], acc[mf][nf][3],
                             al[mf][0], al[mf][1], al[mf][2], al[mf][3],
                             bh[nf][0], bh[nf][1]);
                }
        }
        __syncthreads();
        cur ^= 1;
    }
}

// ---------------------------------------------------------------------------
// K2: h = h1 @ model_W + model_b via HMMA; emits h hi/lo. grid (128,4).
// ---------------------------------------------------------------------------
__global__ void __launch_bounds__(256, 3)
k_gemmh_mm(const float* __restrict__ bm) {
    extern __shared__ char smem[];
    uint32_t sbase = smem_u32(smem);
    int tid = threadIdx.x, wid = tid >> 5, lane = tid & 31;
    int m0 = blockIdx.x * 128;
    int n0 = blockIdx.y * 64;

    float* scat = (float*)(smem + S_CAT2);
    if (tid < 64) scat[tid] = bm[n0 + tid];

    float acc[2][4][4];
#pragma unroll
    for (int mf = 0; mf < 2; mf++)
#pragma unroll
        for (int nf = 0; nf < 4; nf++)
#pragma unroll
            for (int q = 0; q < 4; q++) acc[mf][nf][q] = 0.f;

    hmma_tile_db(sbase, tid, wid, lane,
                 g_h1h, g_h1l, m0,
                 g_mwh + (size_t)n0 * HDIM, g_mwl + (size_t)n0 * HDIM, acc);

    float* stage = (float*)smem;
    const int rw = (wid & 3) * 32;
    const int cw = (wid >> 2) * 32;
    int qr = lane >> 2;
    int qc = (lane & 3) * 2;
#pragma unroll
    for (int mf = 0; mf < 2; mf++)
#pragma unroll
        for (int nf = 0; nf < 4; nf++) {
            int col = cw + nf * 8 + qc;
            int r1 = rw + mf * 16 + qr;
            int r2 = r1 + 8;
            stage[r1 * 65 + col]     = acc[mf][nf][0] + scat[col];
            stage[r1 * 65 + col + 1] = acc[mf][nf][1] + scat[col + 1];
            stage[r2 * 65 + col]     = acc[mf][nf][2] + scat[col];
            stage[r2 * 65 + col + 1] = acc[mf][nf][3] + scat[col + 1];
        }
    __syncthreads();

#pragma unroll
    for (int i = 0; i < 32; i++) {
        int e = tid + i * 256;
        int r = e >> 6;
        int col = e & 63;
        float v = stage[r * 65 + col];
        size_t o = (size_t)(m0 + r) * HDIM + n0 + col;
        __half hi = __float2half_rn(v);
        g_hh[o] = hi;
        g_hl[o] = __float2half_rn(v - __half2float(hi));
    }
}

// ---------------------------------------------------------------------------
// K3: heads via HMMA. grid (128), 256 thr.
// ---------------------------------------------------------------------------
__global__ void __launch_bounds__(256, 3)
k_heads_mm(const float* __restrict__ fcub, const float* __restrict__ fcob,
           float* __restrict__ out) {
    extern __shared__ char smem[];
    uint32_t sbase = smem_u32(smem);
    int tid = threadIdx.x, wid = tid >> 5, lane = tid & 31;
    int m0 = blockIdx.x * 128;

    float acc[2][4][4];
#pragma unroll
    for (int mf = 0; mf < 2; mf++)
#pragma unroll
        for (int nf = 0; nf < 4; nf++)
#pragma unroll
            for (int q = 0; q < 4; q++) acc[mf][nf][q] = 0.f;

    hmma_tile_db(sbase, tid, wid, lane,
                 g_hh, g_hl, m0, g_fwh, g_fwl, acc);

    const int rw = (wid & 3) * 32;
    const int cw = (wid >> 2) * 32;
    int qr = lane >> 2;
    int qc = (lane & 3) * 2;
#pragma unroll
    for (int mf = 0; mf < 2; mf++)
#pragma unroll
        for (int nf = 0; nf < 4; nf++) {
            int col = cw + nf * 8 + qc;
            int r1 = m0 + rw + mf * 16 + qr;
            int r2 = r1 + 8;
#pragma unroll
            for (int e = 0; e < 2; e++) {
                int gc = col + e;
                float bia = (gc < 32) ? fcub[gc] : fcob[gc - 32];
                float v1 = acc[mf][nf][e]     + bia;
                float v2 = acc[mf][nf][2 + e] + bia;
                if (gc < 32) {
                    if (gc >= NCAT) {
                        out[r1 * ODIM + gc] = v1;
                        out[r2 * ODIM + gc] = v2;
                    }
                } else {
                    out[OFF_O + r1 * ODIM + (gc - 32)] = v1;
                    out[OFF_O + r2 * ODIM + (gc - 32)] = v2;
                }
            }
        }
}

// ---------------------------------------------------------------------------
// K4: HMMA logits, 30 FULL tiles. grid (128, 30), 256 thr.
// Fragment-based argmax (shuffle over quad lanes) + single-sync stage for c.
// ---------------------------------------------------------------------------
__global__ void __launch_bounds__(256, 3)
k_logits_mm(const float* __restrict__ catb, float* __restrict__ out) {
    extern __shared__ char smem[];
    uint32_t sbase = smem_u32(smem);
    int tid = threadIdx.x, wid = tid >> 5, lane = tid & 31;
    int ti = blockIdx.y;
    int f  = c_tf2[ti];
    int n0 = c_tn2[ti];
    int m0 = blockIdx.x * 128;

    float* scat = (float*)(smem + S_CAT2);
    if (tid < 64) scat[tid] = catb[f * VPAD + n0 + tid];

    float acc[2][4][4];
#pragma unroll
    for (int mf = 0; mf < 2; mf++)
#pragma unroll
        for (int nf = 0; nf < 4; nf++)
#pragma unroll
            for (int q = 0; q < 4; q++) acc[mf][nf][q] = 0.f;

    hmma_tile_db(sbase, tid, wid, lane,
                 g_hh, g_hl, m0,
                 g_cwh + ((size_t)f * NPAD + n0) * HDIM,
                 g_cwl + ((size_t)f * NPAD + n0) * HDIM, acc);

    float* stage = (float*)smem;
    const int rw = (wid & 3) * 32;
    const int cw = (wid >> 2) * 32;
    int qr = lane >> 2;
    int qc = (lane & 3) * 2;

    // add bias, stage for c, and track per-thread row maxima from fragments
    unsigned long long best1[2], best2[2];   // [mf] rows r1, r2
#pragma unroll
    for (int mf = 0; mf < 2; mf++) { best1[mf] = 0ULL; best2[mf] = 0ULL; }

#pragma unroll
    for (int mf = 0; mf < 2; mf++)
#pragma unroll
        for (int nf = 0; nf < 4; nf++) {
            int col = cw + nf * 8 + qc;
            int r1 = rw + mf * 16 + qr;
            int r2 = r1 + 8;
            float v00 = acc[mf][nf][0] + scat[col];
            float v01 = acc[mf][nf][1] + scat[col + 1];
            float v10 = acc[mf][nf][2] + scat[col];
            float v11 = acc[mf][nf][3] + scat[col + 1];
            stage[r1 * 65 + col]     = v00;
            stage[r1 * 65 + col + 1] = v01;
            stage[r2 * 65 + col]     = v10;
            stage[r2 * 65 + col + 1] = v11;
#pragma unroll
            for (int e = 0; e < 2; e++) {
                float va = e ? v01 : v00;
                float vb = e ? v11 : v10;
                int gc = n0 + col + e;
                unsigned ua = __float_as_uint(va);
                unsigned ka = (ua & 0x80000000u) ? ~ua : (ua | 0x80000000u);
                unsigned long long pa =
                    ((unsigned long long)ka << 32) | (unsigned long long)(1023 - gc);
                if (pa > best1[mf]) best1[mf] = pa;
                unsigned ub = __float_as_uint(vb);
                unsigned kb = (ub & 0x80000000u) ? ~ub : (ub | 0x80000000u);
                unsigned long long pb =
                    ((unsigned long long)kb << 32) | (unsigned long long)(1023 - gc);
                if (pb > best2[mf]) best2[mf] = pb;
            }
        }
    // reduce across the 4 lanes of each quad-row (lane = qr*4 + qi)
#pragma unroll
    for (int mf = 0; mf < 2; mf++) {
#pragma unroll
        for (int d = 1; d < 4; d <<= 1) {
            unsigned long long o1 = __shfl_xor_sync(0xFFFFFFFFu, best1[mf], d);
            unsigned long long o2 = __shfl_xor_sync(0xFFFFFFFFu, best2[mf], d);
            if (o1 > best1[mf]) best1[mf] = o1;
            if (o2 > best2[mf]) best2[mf] = o2;
        }
        if ((lane & 3) == 0) {
            int r1 = rw + mf * 16 + qr;
            atomicMax(&g_amax[(size_t)f * BT + m0 + r1], best1[mf]);
            atomicMax(&g_amax[(size_t)f * BT + m0 + r1 + 8], best2[mf]);
        }
    }
    __syncthreads();

    // Coalesced write-out of c tile
    float* cbase = out + OFF_C + (size_t)f * BT * VPAD;
#pragma unroll
    for (int i = 0; i < 32; i++) {
        int e = tid + i * 256;
        int r = e >> 6;
        int col = e & 63;
        cbase[(size_t)(m0 + r) * VPAD + n0 + col] = stage[r * 65 + col];
    }
}

// ---------------------------------------------------------------------------
// K4b: the 8 "+1" columns; ALSO initializes g_amax (plain store, runs before
// logits). h reconstructed from hi+lo splits.
// ---------------------------------------------------------------------------
__global__ void __launch_bounds__(256)
k_extra(const float* __restrict__ catW, const float* __restrict__ catb,
        float* __restrict__ out) {
    __shared__ float sW[8][257];
    __shared__ float sh[32][257];
    int tid = threadIdx.x;
    int row0 = blockIdx.x * 32;

#pragma unroll
    for (int i = 0; i < 8; i++) {
        int id = tid + i * 256;
        int f = id >> 8;
        int k = id & 255;
        sW[f][k] = catW[((size_t)f * HDIM + k) * VPAD + c_colf[f]];
    }
#pragma unroll
    for (int i = 0; i < 32; i++) {
        int id = tid + i * 256;
        int r = id >> 8;
        int k = id & 255;
        size_t o = (size_t)(row0 + r) * HDIM + k;
        sh[r][k] = __half2float(g_hh[o]) + __half2float(g_hl[o]);
    }
    __syncthreads();

    int f = tid & 7;
    int r = tid >> 3;
    int col = c_colf[f];
    float s = catb[f * VPAD + col];
#pragma unroll 8
    for (int k = 0; k < HDIM; k++) s += sh[r][k] * sW[f][k];

    out[OFF_C + ((size_t)f * BT + row0 + r) * VPAD + col] = s;

    unsigned u = __float_as_uint(s);
    unsigned key = (u & 0x80000000u) ? ~u : (u | 0x80000000u);
    unsigned long long pk =
        ((unsigned long long)key << 32) | (unsigned long long)(1023 - col);
    g_amax[(size_t)f * BT + row0 + r] = pk;     // plain store: the initializer
}

// ---------------------------------------------------------------------------
// K5: fill invalid region of c with -1e30
// ---------------------------------------------------------------------------
__global__ void k_fill(float* __restrict__ out) {
    int f = blockIdx.y;
    int ncols = c_ncols[f];
    if (ncols >= VPAD) return;
    int r0 = blockIdx.x * 32;
    float* cbase = out + OFF_C + (size_t)f * BT * VPAD;
#pragma unroll 4
    for (int rr = 0; rr < 32; rr++) {
        size_t rowoff = (size_t)(r0 + rr) * VPAD;
        for (int col = ncols + threadIdx.x; col < VPAD; col += blockDim.x)
            cbase[rowoff + col] = NEGINF;
    }
}

// ---------------------------------------------------------------------------
// K6: decode argmax into u[:, :, 0:8]
// ---------------------------------------------------------------------------
__global__ void k_writearg(float* __restrict__ out) {
    int i = blockIdx.x * blockDim.x + threadIdx.x;
    if (i >= NCAT * BT) return;
    int f  = i / BT;
    int bt = i - f * BT;
    unsigned long long p = g_amax[i];
    int idx = 1023 - (int)(p & 0xFFFFFFFFu);
    out[bt * ODIM + f] = (float)idx - 1.0f;
}

// ---------------------------------------------------------------------------
extern "C" void kernel_launch(void* const* d_in, const int* in_sizes, int n_in,
                              void* d_out, int out_size) {
    const float* x       = (const float*)d_in[0];
    const float* embs    = (const float*)d_in[1];
    const float* feat_W  = (const float*)d_in[2];
    const float* feat_b  = (const float*)d_in[3];
    const float* model_W = (const float*)d_in[4];
    const float* model_b = (const float*)d_in[5];
    const float* fcu_W   = (const float*)d_in[6];
    const float* fcu_b   = (const float*)d_in[7];
    const float* fco_W   = (const float*)d_in[8];
    const float* fco_b   = (const float*)d_in[9];
    const float* cat_W   = (const float*)d_in[10];
    const float* cat_b   = (const float*)d_in[11];
    float* out = (float*)d_out;

    cudaFuncSetAttribute(k_logits_mm, cudaFuncAttributeMaxDynamicSharedMemorySize, SMEM_DB);
    cudaFuncSetAttribute(k_heads_mm, cudaFuncAttributeMaxDynamicSharedMemorySize, SMEM_DB);
    cudaFuncSetAttribute(k_gemmh_mm, cudaFuncAttributeMaxDynamicSharedMemorySize, SMEM_DB);

    k_prep_catw<<<dim3(72, NCAT), 256>>>(cat_W);
    k_prep_small<<<HDIM + 64, 256>>>(model_W, fcu_W, fco_W);
    k_embed<<<BT / 4, 256>>>(x, embs, feat_W, feat_b);
    k_gemmh_mm<<<dim3(BT / 128, 4), 256, SMEM_DB>>>(model_b);
    k_extra<<<BT / 32, 256>>>(cat_W, cat_b, out);      // initializes g_amax
    k_heads_mm<<<BT / 128, 256, SMEM_DB>>>(fcu_b, fco_b, out);
    k_logits_mm<<<dim3(BT / 128, 30), 256, SMEM_DB>>>(cat_b, out);
    k_fill<<<dim3(BT / 32, NCAT), 256>>>(out);
    k_writearg<<<(NCAT * BT + 255) / 256, 256>>>(out);
}

// round 15
// speedup vs baseline: 1.0426x; 1.0426x over previous
#include <cuda_runtime.h>
#include <cuda_bf16.h>
#include <cuda_fp16.h>
#include <cstdint>

// Problem constants
#define BT      16384           // B*T = 32*512
#define HDIM    256
#define NCAT    8
#define NCONT   24
#define VPAD    513
#define ODIM    32
#define NEGINF  (-1e30f)
#define NPAD    576             // padded vocab cols for catWT

// Output layout (flattened tuple (u, o, c)):
#define OFF_O   (BT * ODIM)
#define OFF_C   (2 * BT * ODIM)

// Scratch (static __device__ arrays — no allocation allowed)
__device__ __align__(16) __half g_h1h[BT * HDIM];  // h1 split hi
__device__ __align__(16) __half g_h1l[BT * HDIM];  // h1 split lo
__device__ __align__(16) __half g_hh[BT * HDIM];   // h split hi (f16)
__device__ __align__(16) __half g_hl[BT * HDIM];   // h split lo (f16)
__device__ __align__(16) __half g_mwh[HDIM * HDIM]; // model_W^T hi [n][k]
__device__ __align__(16) __half g_mwl[HDIM * HDIM]; // model_W^T lo [n][k]
__device__ __align__(16) __half g_cwh[NCAT * NPAD * HDIM]; // cat_W^T hi [n][k]
__device__ __align__(16) __half g_cwl[NCAT * NPAD * HDIM]; // cat_W^T lo [n][k]
__device__ __align__(16) __half g_fwh[64 * HDIM];  // [fcu|fco]^T hi [j][k]
__device__ __align__(16) __half g_fwl[64 * HDIM];  // [fcu|fco]^T lo [j][k]
__device__ unsigned long long g_amax[NCAT * BT];   // packed (key<<32)|(1023-idx)

// 30 FULL (f, n0) tiles of 64 valid cols (vocab+1 = k*64+1 for every f)
__constant__ signed char c_tf2[30] = {0,0,0,0,0,0,0,0, 1,1,1,1,1,1,1,1,
                                      2,2,2,2, 3,3,3,3, 4,4, 5,5, 6, 7};
__constant__ short c_tn2[30] = {0,64,128,192,256,320,384,448,
                                0,64,128,192,256,320,384,448,
                                0,64,128,192, 0,64,128,192,
                                0,64, 0,64, 0, 0};
__constant__ short c_colf[8] = {512,512,256,256,128,128,64,64};  // the "+1" col per f
// 34 fill chunks of 64 cols covering the -1e30 region (cols vocab+1..512)
__constant__ signed char c_ff[34] = {2,2,2,2, 3,3,3,3, 4,4,4,4,4,4,
                                     5,5,5,5,5,5, 6,6,6,6,6,6,6, 7,7,7,7,7,7,7};
__constant__ short c_fc0[34] = {257,321,385,449, 257,321,385,449,
                                129,193,257,321,385,449, 129,193,257,321,385,449,
                                65,129,193,257,321,385,449, 65,129,193,257,321,385,449};

// ---------------------------------------------------------------------------
// Warp-MMA helpers (baseline PTX, works on .target sm_100)
// ---------------------------------------------------------------------------
__device__ __forceinline__ uint32_t smem_u32(const void* p) {
    uint32_t a;
    asm("{ .reg .u64 t; cvta.to.shared.u64 t, %1; cvt.u32.u64 %0, t; }"
        : "=r"(a) : "l"(p));
    return a;
}

#define LDSM_X4(r0, r1, r2, r3, addr) \
    asm volatile("ldmatrix.sync.aligned.m8n8.x4.shared.b16 {%0,%1,%2,%3}, [%4];" \
        : "=r"(r0), "=r"(r1), "=r"(r2), "=r"(r3) : "r"(addr))

#define MMA16816(c0, c1, c2, c3, a0, a1, a2, a3, b0, b1) \
    asm volatile("mma.sync.aligned.m16n8k16.row.col.f32.f16.f16.f32 " \
        "{%0,%1,%2,%3}, {%4,%5,%6,%7}, {%8,%9}, {%0,%1,%2,%3};" \
        : "+f"(c0), "+f"(c1), "+f"(c2), "+f"(c3) \
        : "r"(a0), "r"(a1), "r"(a2), "r"(a3), "r"(b0), "r"(b1))

#define CP_A16(dst, srcp) \
    asm volatile("cp.async.cg.shared.global [%0], [%1], 16;" \
        :: "r"(dst), "l"(__cvta_generic_to_global(srcp)) : "memory")
#define CP_COMMIT() asm volatile("cp.async.commit_group;" ::: "memory")

// ---------------------------------------------------------------------------
// K_prep: cat_W [8,256,513] -> transposed padded f16 hi/lo [8,576,256]
// ---------------------------------------------------------------------------
__global__ void __launch_bounds__(256)
k_prep_catw(const float* __restrict__ catW) {
    __shared__ float tile[32][65];
    int bt = blockIdx.x;
    int f  = blockIdx.y;
    int k0 = (bt % 8) * 32;
    int n0 = (bt / 8) * 64;
    int tid = threadIdx.x;

    int n_local = tid & 63;
    int k_local = tid >> 6;              // 0..3
#pragma unroll
    for (int p = 0; p < 8; p++) {
        int k = k_local + p * 4;
        int n = n0 + n_local;
        tile[k][n_local] = (n < VPAD)
            ? catW[((size_t)f * HDIM + k0 + k) * VPAD + n] : 0.f;
    }
    __syncthreads();

    int k2 = tid & 31;
    int nl = tid >> 5;                   // 0..7
#pragma unroll
    for (int p = 0; p < 8; p++) {
        int n = nl + p * 8;
        float v = tile[k2][n];
        __half hi = __float2half_rn(v);
        __half lo = __float2half_rn(v - __half2float(hi));
        size_t o = ((size_t)f * NPAD + n0 + n) * HDIM + k0 + k2;
        g_cwh[o] = hi;
        g_cwl[o] = lo;
    }
}

// K_prep2: merged small preps — model_W^T (blocks 0..255) and [fcu|fco]^T
__global__ void k_prep_small(const float* __restrict__ Wm,
                             const float* __restrict__ fcuW,
                             const float* __restrict__ fcoW) {
    int b = blockIdx.x, k = threadIdx.x;
    if (b < HDIM) {
        float v = Wm[k * HDIM + b];
        __half hi = __float2half_rn(v);
        __half lo = __float2half_rn(v - __half2float(hi));
        g_mwh[b * HDIM + k] = hi;
        g_mwl[b * HDIM + k] = lo;
    } else {
        int j = b - HDIM;
        float v = (j < 32) ? fcuW[k * ODIM + j] : fcoW[k * ODIM + (j - 32)];
        __half hi = __float2half_rn(v);
        __half lo = __float2half_rn(v - __half2float(hi));
        g_fwh[j * HDIM + k] = hi;
        g_fwl[j * HDIM + k] = lo;
    }
}

// ---------------------------------------------------------------------------
// K1: h1 = mean(embs gather) + x_cont @ feat_W + feat_b -> split f16 hi/lo
// ---------------------------------------------------------------------------
__global__ void __launch_bounds__(256)
k_embed(const float* __restrict__ x,
        const float* __restrict__ embs,
        const float* __restrict__ feat_W,
        const float* __restrict__ feat_b) {
    int c   = threadIdx.x;
    int bt0 = blockIdx.x * 4;
    __shared__ float sx[4][32];
    if (c < 128) {
        int t = c >> 5, j = c & 31;
        sx[t][j] = x[(bt0 + t) * 32 + j];
    }
    __syncthreads();

    float fw[NCONT];
#pragma unroll
    for (int j = 0; j < NCONT; j++) fw[j] = feat_W[j * HDIM + c];
    float fb = feat_b[c];

#pragma unroll
    for (int t = 0; t < 4; t++) {
        float e = 0.f;
#pragma unroll
        for (int f = 0; f < NCAT; f++) {
            int id = (int)sx[t][f] + 1;
            e += embs[((size_t)f * VPAD + id) * HDIM + c];
        }
        float acc = fb + e * 0.125f;
#pragma unroll
        for (int j = 0; j < NCONT; j++)
            acc += sx[t][NCAT + j] * fw[j];
        __half hi = __float2half_rn(acc);
        __half lo = __float2half_rn(acc - __half2float(hi));
        g_h1h[(size_t)(bt0 + t) * HDIM + c] = hi;
        g_h1l[(size_t)(bt0 + t) * HDIM + c] = lo;
    }
}

// ---------------------------------------------------------------------------
// Double-buffered smem layout (R12 config: K-chunk 64, pitch 72)
// Per buffer: AH 0..18431, AL 18432..36863, BH 36864..46079, BL 46080..55295
// ---------------------------------------------------------------------------
#define APITCH 72
#define BUF_SZ 55296
#define O_AL   18432
#define O_BH   36864
#define O_BL   46080
#define S_CAT2 (2 * BUF_SZ)             // 110592
#define SMEM_DB (S_CAT2 + 256)          // 110848
// stage (float[128][65] = 33280 B) reuses buffer0 after the MMA loop

// ---------------------------------------------------------------------------
// HMMA core 128x64, cp.async double-buffered, 4 chunks of K=64 (256 threads)
// ---------------------------------------------------------------------------
__device__ __forceinline__ void hmma_tile_db(
    uint32_t sbase, int tid, int wid, int lane,
    const __half* __restrict__ Ah, const __half* __restrict__ Al, int m0,
    const __half* __restrict__ Bh0, const __half* __restrict__ Bl0,
    float acc[2][4][4])
{
    const int rw = (wid & 3) * 32;
    const int cw = (wid >> 2) * 32;
    uint32_t a_row = (uint32_t)(lane & 15);
    uint32_t a_c8  = (uint32_t)((lane >> 4) * 8);
    uint32_t b_row = (uint32_t)((lane & 7) + ((lane >> 3) & 1) * 8);
    uint32_t b_c8  = (uint32_t)((lane >> 4) * 8);

    auto issue = [&](int buf, int kc) {
        uint32_t base = sbase + buf * BUF_SZ;
#pragma unroll
        for (int i = 0; i < 4; i++) {
            int id = tid + i * 256;
            int r  = id >> 3;
            int c8 = (id & 7) * 8;
            size_t src = (size_t)(m0 + r) * HDIM + kc + c8;
            uint32_t off = (uint32_t)((r * APITCH + c8) * 2);
            CP_A16(base + off,        Ah + src);
            CP_A16(base + O_AL + off, Al + src);
        }
#pragma unroll
        for (int i = 0; i < 2; i++) {
            int id = tid + i * 256;
            int r  = id >> 3;
            int c8 = (id & 7) * 8;
            size_t src = (size_t)r * HDIM + kc + c8;
            uint32_t off = (uint32_t)((r * APITCH + c8) * 2);
            CP_A16(base + O_BH + off, Bh0 + src);
            CP_A16(base + O_BL + off, Bl0 + src);
        }
        CP_COMMIT();
    };

    issue(0, 0);
    int cur = 0;
#pragma unroll
    for (int ki = 0; ki < 4; ki++) {
        if (ki < 3) {
            issue(cur ^ 1, (ki + 1) * 64);
            asm volatile("cp.async.wait_group 1;" ::: "memory");
        } else {
            asm volatile("cp.async.wait_group 0;" ::: "memory");
        }
        __syncthreads();

        uint32_t bA  = sbase + cur * BUF_SZ;
        uint32_t bAl = bA + O_AL;
        uint32_t bBh = bA + O_BH;
        uint32_t bBl = bA + O_BL;
#pragma unroll
        for (int ks = 0; ks < 4; ks++) {
            int kk = ks * 16;
            uint32_t ah[2][4], al[2][4];
#pragma unroll
            for (int mf = 0; mf < 2; mf++) {
                uint32_t off = ((rw + mf * 16 + a_row) * APITCH + kk + a_c8) * 2;
                LDSM_X4(ah[mf][0], ah[mf][1], ah[mf][2], ah[mf][3], bA  + off);
                LDSM_X4(al[mf][0], al[mf][1], al[mf][2], al[mf][3], bAl + off);
            }
            uint32_t bh[4][2], bl[4][2];
#pragma unroll
            for (int g = 0; g < 2; g++) {
                uint32_t off = ((cw + g * 16 + b_row) * APITCH + kk + b_c8) * 2;
                uint32_t r0, r1, r2, r3;
                LDSM_X4(r0, r1, r2, r3, bBh + off);
                bh[g * 2 + 0][0] = r0; bh[g * 2 + 0][1] = r2;
                bh[g * 2 + 1][0] = r1; bh[g * 2 + 1][1] = r3;
                LDSM_X4(r0, r1, r2, r3, bBl + off);
                bl[g * 2 + 0][0] = r0; bl[g * 2 + 0][1] = r2;
                bl[g * 2 + 1][0] = r1; bl[g * 2 + 1][1] = r3;
            }
#pragma unroll
            for (int mf = 0; mf < 2; mf++)
#pragma unroll
                for (int nf = 0; nf < 4; nf++) {
                    MMA16816(acc[mf][nf][0], acc[mf][nf][1], acc[mf][nf][2], acc[mf][nf][3],
                             ah[mf][0], ah[mf][1], ah[mf][2], ah[mf][3],
                             bh[nf][0], bh[nf][1]);
                    MMA16816(acc[mf][nf][0], acc[mf][nf][1], acc[mf][nf][2], acc[mf][nf][3],
                             ah[mf][0], ah[mf][1], ah[mf][2], ah[mf][3],
                             bl[nf][0], bl[nf][1]);
                    MMA16816(acc[mf][nf][0], acc[mf][nf][1], acc[mf][nf][2], acc[mf][nf][3],
                             al[mf][0], al[mf][1], al[mf][2], al[mf][3],
                             bh[nf][0], bh[nf][1]);
                }
        }
        __syncthreads();
        cur ^= 1;
    }
}

// ---------------------------------------------------------------------------
// K2: h = h1 @ model_W + model_b via HMMA; emits h hi/lo. grid (128,4).
// ---------------------------------------------------------------------------
__global__ void __launch_bounds__(256)
k_gemmh_mm(const float* __restrict__ bm) {
    extern __shared__ char smem[];
    uint32_t sbase = smem_u32(smem);
    int tid = threadIdx.x, wid = tid >> 5, lane = tid & 31;
    int m0 = blockIdx.x * 128;
    int n0 = blockIdx.y * 64;

    float* scat = (float*)(smem + S_CAT2);
    if (tid < 64) scat[tid] = bm[n0 + tid];

    float acc[2][4][4];
#pragma unroll
    for (int mf = 0; mf < 2; mf++)
#pragma unroll
        for (int nf = 0; nf < 4; nf++)
#pragma unroll
            for (int q = 0; q < 4; q++) acc[mf][nf][q] = 0.f;

    hmma_tile_db(sbase, tid, wid, lane,
                 g_h1h, g_h1l, m0,
                 g_mwh + (size_t)n0 * HDIM, g_mwl + (size_t)n0 * HDIM, acc);

    float* stage = (float*)smem;
    const int rw = (wid & 3) * 32;
    const int cw = (wid >> 2) * 32;
    int qr = lane >> 2;
    int qc = (lane & 3) * 2;
#pragma unroll
    for (int mf = 0; mf < 2; mf++)
#pragma unroll
        for (int nf = 0; nf < 4; nf++) {
            int col = cw + nf * 8 + qc;
            int r1 = rw + mf * 16 + qr;
            int r2 = r1 + 8;
            stage[r1 * 65 + col]     = acc[mf][nf][0] + scat[col];
            stage[r1 * 65 + col + 1] = acc[mf][nf][1] + scat[col + 1];
            stage[r2 * 65 + col]     = acc[mf][nf][2] + scat[col];
            stage[r2 * 65 + col + 1] = acc[mf][nf][3] + scat[col + 1];
        }
    __syncthreads();

#pragma unroll
    for (int i = 0; i < 32; i++) {
        int e = tid + i * 256;
        int r = e >> 6;
        int col = e & 63;
        float v = stage[r * 65 + col];
        size_t o = (size_t)(m0 + r) * HDIM + n0 + col;
        __half hi = __float2half_rn(v);
        g_hh[o] = hi;
        g_hl[o] = __float2half_rn(v - __half2float(hi));
    }
}

// ---------------------------------------------------------------------------
// K3: heads via HMMA. grid (128), 256 thr.
// ---------------------------------------------------------------------------
__global__ void __launch_bounds__(256)
k_heads_mm(const float* __restrict__ fcub, const float* __restrict__ fcob,
           float* __restrict__ out) {
    extern __shared__ char smem[];
    uint32_t sbase = smem_u32(smem);
    int tid = threadIdx.x, wid = tid >> 5, lane = tid & 31;
    int m0 = blockIdx.x * 128;

    float acc[2][4][4];
#pragma unroll
    for (int mf = 0; mf < 2; mf++)
#pragma unroll
        for (int nf = 0; nf < 4; nf++)
#pragma unroll
            for (int q = 0; q < 4; q++) acc[mf][nf][q] = 0.f;

    hmma_tile_db(sbase, tid, wid, lane,
                 g_hh, g_hl, m0, g_fwh, g_fwl, acc);

    const int rw = (wid & 3) * 32;
    const int cw = (wid >> 2) * 32;
    int qr = lane >> 2;
    int qc = (lane & 3) * 2;
#pragma unroll
    for (int mf = 0; mf < 2; mf++)
#pragma unroll
        for (int nf = 0; nf < 4; nf++) {
            int col = cw + nf * 8 + qc;
            int r1 = m0 + rw + mf * 16 + qr;
            int r2 = r1 + 8;
#pragma unroll
            for (int e = 0; e < 2; e++) {
                int gc = col + e;
                float bia = (gc < 32) ? fcub[gc] : fcob[gc - 32];
                float v1 = acc[mf][nf][e]     + bia;
                float v2 = acc[mf][nf][2 + e] + bia;
                if (gc < 32) {
                    if (gc >= NCAT) {
                        out[r1 * ODIM + gc] = v1;
                        out[r2 * ODIM + gc] = v2;
                    }
                } else {
                    out[OFF_O + r1 * ODIM + (gc - 32)] = v1;
                    out[OFF_O + r2 * ODIM + (gc - 32)] = v2;
                }
            }
        }
}

// ---------------------------------------------------------------------------
// K4: HMMA logits, 30 FULL tiles. grid (128, 30), 256 thr.
// Fragment argmax + c write + fused -1e30 fill chunks (hidden behind MMA).
// ---------------------------------------------------------------------------
__global__ void __launch_bounds__(256)
k_logits_mm(const float* __restrict__ catb, float* __restrict__ out) {
    extern __shared__ char smem[];
    uint32_t sbase = smem_u32(smem);
    int tid = threadIdx.x, wid = tid >> 5, lane = tid & 31;
    int ti = blockIdx.y;
    int f  = c_tf2[ti];
    int n0 = c_tn2[ti];
    int m0 = blockIdx.x * 128;

    float* scat = (float*)(smem + S_CAT2);
    if (tid < 64) scat[tid] = catb[f * VPAD + n0 + tid];

    float acc[2][4][4];
#pragma unroll
    for (int mf = 0; mf < 2; mf++)
#pragma unroll
        for (int nf = 0; nf < 4; nf++)
#pragma unroll
            for (int q = 0; q < 4; q++) acc[mf][nf][q] = 0.f;

    hmma_tile_db(sbase, tid, wid, lane,
                 g_hh, g_hl, m0,
                 g_cwh + ((size_t)f * NPAD + n0) * HDIM,
                 g_cwl + ((size_t)f * NPAD + n0) * HDIM, acc);

    float* stage = (float*)smem;
    const int rw = (wid & 3) * 32;
    const int cw = (wid >> 2) * 32;
    int qr = lane >> 2;
    int qc = (lane & 3) * 2;

    // bias + stage + per-thread row maxima from fragments
    unsigned long long best1[2], best2[2];
#pragma unroll
    for (int mf = 0; mf < 2; mf++) { best1[mf] = 0ULL; best2[mf] = 0ULL; }

#pragma unroll
    for (int mf = 0; mf < 2; mf++)
#pragma unroll
        for (int nf = 0; nf < 4; nf++) {
            int col = cw + nf * 8 + qc;
            int r1 = rw + mf * 16 + qr;
            int r2 = r1 + 8;
            float v00 = acc[mf][nf][0] + scat[col];
            float v01 = acc[mf][nf][1] + scat[col + 1];
            float v10 = acc[mf][nf][2] + scat[col];
            float v11 = acc[mf][nf][3] + scat[col + 1];
            stage[r1 * 65 + col]     = v00;
            stage[r1 * 65 + col + 1] = v01;
            stage[r2 * 65 + col]     = v10;
            stage[r2 * 65 + col + 1] = v11;
#pragma unroll
            for (int e = 0; e < 2; e++) {
                float va = e ? v01 : v00;
                float vb = e ? v11 : v10;
                int gc = n0 + col + e;
                unsigned ua = __float_as_uint(va);
                unsigned ka = (ua & 0x80000000u) ? ~ua : (ua | 0x80000000u);
                unsigned long long pa =
                    ((unsigned long long)ka << 32) | (unsigned long long)(1023 - gc);
                if (pa > best1[mf]) best1[mf] = pa;
                unsigned ub = __float_as_uint(vb);
                unsigned kb = (ub & 0x80000000u) ? ~ub : (ub | 0x80000000u);
                unsigned long long pb =
                    ((unsigned long long)kb << 32) | (unsigned long long)(1023 - gc);
                if (pb > best2[mf]) best2[mf] = pb;
            }
        }
    // reduce across the 4 lanes of each quad-row
#pragma unroll
    for (int mf = 0; mf < 2; mf++) {
#pragma unroll
        for (int d = 1; d < 4; d <<= 1) {
            unsigned long long o1 = __shfl_xor_sync(0xFFFFFFFFu, best1[mf], d);
            unsigned long long o2 = __shfl_xor_sync(0xFFFFFFFFu, best2[mf], d);
            if (o1 > best1[mf]) best1[mf] = o1;
            if (o2 > best2[mf]) best2[mf] = o2;
        }
        if ((lane & 3) == 0) {
            int r1 = rw + mf * 16 + qr;
            atomicMax(&g_amax[(size_t)f * BT + m0 + r1], best1[mf]);
            atomicMax(&g_amax[(size_t)f * BT + m0 + r1 + 8], best2[mf]);
        }
    }
    __syncthreads();

    // Coalesced write-out of c tile
    float* cbase = out + OFF_C + (size_t)f * BT * VPAD;
#pragma unroll
    for (int i = 0; i < 32; i++) {
        int e = tid + i * 256;
        int r = e >> 6;
        int col = e & 63;
        cbase[(size_t)(m0 + r) * VPAD + n0 + col] = stage[r * 65 + col];
    }

    // Fused fill: this block handles chunk ti (and ti+30 if present):
    // 64 cols x 128 rows of -1e30 in feature c_ff's invalid region.
    for (int cidx = ti; cidx < 34; cidx += 30) {
        int ff = c_ff[cidx];
        int c0 = c_fc0[cidx];
        float* fb = out + OFF_C + (size_t)ff * BT * VPAD;
#pragma unroll
        for (int i = 0; i < 32; i++) {
            int e = tid + i * 256;
            int r = e >> 6;
            int col = e & 63;
            fb[(size_t)(m0 + r) * VPAD + c0 + col] = NEGINF;
        }
    }
}

// ---------------------------------------------------------------------------
// K4b: the 8 "+1" columns; ALSO initializes g_amax (plain store, runs before
// logits). h reconstructed from hi+lo splits.
// ---------------------------------------------------------------------------
__global__ void __launch_bounds__(256)
k_extra(const float* __restrict__ catW, const float* __restrict__ catb,
        float* __restrict__ out) {
    __shared__ float sW[8][257];
    __shared__ float sh[32][257];
    int tid = threadIdx.x;
    int row0 = blockIdx.x * 32;

#pragma unroll
    for (int i = 0; i < 8; i++) {
        int id = tid + i * 256;
        int f = id >> 8;
        int k = id & 255;
        sW[f][k] = catW[((size_t)f * HDIM + k) * VPAD + c_colf[f]];
    }
#pragma unroll
    for (int i = 0; i < 32; i++) {
        int id = tid + i * 256;
        int r = id >> 8;
        int k = id & 255;
        size_t o = (size_t)(row0 + r) * HDIM + k;
        sh[r][k] = __half2float(g_hh[o]) + __half2float(g_hl[o]);
    }
    __syncthreads();

    int f = tid & 7;
    int r = tid >> 3;
    int col = c_colf[f];
    float s = catb[f * VPAD + col];
#pragma unroll 8
    for (int k = 0; k < HDIM; k++) s += sh[r][k] * sW[f][k];

    out[OFF_C + ((size_t)f * BT + row0 + r) * VPAD + col] = s;

    unsigned u = __float_as_uint(s);
    unsigned key = (u & 0x80000000u) ? ~u : (u | 0x80000000u);
    unsigned long long pk =
        ((unsigned long long)key << 32) | (unsigned long long)(1023 - col);
    g_amax[(size_t)f * BT + row0 + r] = pk;     // plain store: the initializer
}

// ---------------------------------------------------------------------------
// K6: decode argmax into u[:, :, 0:8]
// ---------------------------------------------------------------------------
__global__ void k_writearg(float* __restrict__ out) {
    int i = blockIdx.x * blockDim.x + threadIdx.x;
    if (i >= NCAT * BT) return;
    int f  = i / BT;
    int bt = i - f * BT;
    unsigned long long p = g_amax[i];
    int idx = 1023 - (int)(p & 0xFFFFFFFFu);
    out[bt * ODIM + f] = (float)idx - 1.0f;
}

// ---------------------------------------------------------------------------
extern "C" void kernel_launch(void* const* d_in, const int* in_sizes, int n_in,
                              void* d_out, int out_size) {
    const float* x       = (const float*)d_in[0];
    const float* embs    = (const float*)d_in[1];
    const float* feat_W  = (const float*)d_in[2];
    const float* feat_b  = (const float*)d_in[3];
    const float* model_W = (const float*)d_in[4];
    const float* model_b = (const float*)d_in[5];
    const float* fcu_W   = (const float*)d_in[6];
    const float* fcu_b   = (const float*)d_in[7];
    const float* fco_W   = (const float*)d_in[8];
    const float* fco_b   = (const float*)d_in[9];
    const float* cat_W   = (const float*)d_in[10];
    const float* cat_b   = (const float*)d_in[11];
    float* out = (float*)d_out;

    cudaFuncSetAttribute(k_logits_mm, cudaFuncAttributeMaxDynamicSharedMemorySize, SMEM_DB);
    cudaFuncSetAttribute(k_heads_mm, cudaFuncAttributeMaxDynamicSharedMemorySize, SMEM_DB);
    cudaFuncSetAttribute(k_gemmh_mm, cudaFuncAttributeMaxDynamicSharedMemorySize, SMEM_DB);

    k_prep_catw<<<dim3(72, NCAT), 256>>>(cat_W);
    k_prep_small<<<HDIM + 64, 256>>>(model_W, fcu_W, fco_W);
    k_embed<<<BT / 4, 256>>>(x, embs, feat_W, feat_b);
    k_gemmh_mm<<<dim3(BT / 128, 4), 256, SMEM_DB>>>(model_b);
    k_extra<<<BT / 32, 256>>>(cat_W, cat_b, out);      // initializes g_amax
    k_heads_mm<<<BT / 128, 256, SMEM_DB>>>(fcu_b, fco_b, out);
    k_logits_mm<<<dim3(BT / 128, 30), 256, SMEM_DB>>>(cat_b, out);
    k_writearg<<<(NCAT * BT + 255) / 256, 256>>>(out);
}

// round 16
// speedup vs baseline: 1.0652x; 1.0217x over previous
#include <cuda_runtime.h>
#include <cuda_bf16.h>
#include <cuda_fp16.h>
#include <cstdint>

// Problem constants
#define BT      16384           // B*T = 32*512
#define HDIM    256
#define NCAT    8
#define NCONT   24
#define VPAD    513
#define ODIM    32
#define NEGINF  (-1e30f)
#define NPAD    576             // padded vocab cols for catWT

// Output layout (flattened tuple (u, o, c)):
#define OFF_O   (BT * ODIM)
#define OFF_C   (2 * BT * ODIM)

// Scratch (static __device__ arrays — no allocation allowed)
__device__ __align__(16) __half g_h1h[BT * HDIM];  // h1 split hi
__device__ __align__(16) __half g_h1l[BT * HDIM];  // h1 split lo
__device__ __align__(16) __half g_hh[BT * HDIM];   // h split hi (f16)
__device__ __align__(16) __half g_hl[BT * HDIM];   // h split lo (f16)
__device__ __align__(16) __half g_mwh[HDIM * HDIM]; // model_W^T hi [n][k]
__device__ __align__(16) __half g_mwl[HDIM * HDIM]; // model_W^T lo [n][k]
__device__ __align__(16) __half g_cwh[NCAT * NPAD * HDIM]; // cat_W^T hi [n][k]
__device__ __align__(16) __half g_cwl[NCAT * NPAD * HDIM]; // cat_W^T lo [n][k]
__device__ __align__(16) __half g_fwh[64 * HDIM];  // [fcu|fco]^T hi [j][k]
__device__ __align__(16) __half g_fwl[64 * HDIM];  // [fcu|fco]^T lo [j][k]
__device__ unsigned long long g_amax[NCAT * BT];   // packed (key<<32)|(1023-idx)

// 30 FULL (f, n0) tiles of 64 valid cols (vocab+1 = k*64+1 for every f)
__constant__ signed char c_tf2[30] = {0,0,0,0,0,0,0,0, 1,1,1,1,1,1,1,1,
                                      2,2,2,2, 3,3,3,3, 4,4, 5,5, 6, 7};
__constant__ short c_tn2[30] = {0,64,128,192,256,320,384,448,
                                0,64,128,192,256,320,384,448,
                                0,64,128,192, 0,64,128,192,
                                0,64, 0,64, 0, 0};
__constant__ short c_colf[8] = {512,512,256,256,128,128,64,64};  // the "+1" col per f
// 34 fill chunks of 64 cols covering the -1e30 region (cols vocab+1..512)
__constant__ signed char c_ff[34] = {2,2,2,2, 3,3,3,3, 4,4,4,4,4,4,
                                     5,5,5,5,5,5, 6,6,6,6,6,6,6, 7,7,7,7,7,7,7};
__constant__ short c_fc0[34] = {257,321,385,449, 257,321,385,449,
                                129,193,257,321,385,449, 129,193,257,321,385,449,
                                65,129,193,257,321,385,449, 65,129,193,257,321,385,449};

// ---------------------------------------------------------------------------
// Warp-MMA helpers (baseline PTX, works on .target sm_100)
// ---------------------------------------------------------------------------
__device__ __forceinline__ uint32_t smem_u32(const void* p) {
    uint32_t a;
    asm("{ .reg .u64 t; cvta.to.shared.u64 t, %1; cvt.u32.u64 %0, t; }"
        : "=r"(a) : "l"(p));
    return a;
}

#define LDSM_X4(r0, r1, r2, r3, addr) \
    asm volatile("ldmatrix.sync.aligned.m8n8.x4.shared.b16 {%0,%1,%2,%3}, [%4];" \
        : "=r"(r0), "=r"(r1), "=r"(r2), "=r"(r3) : "r"(addr))

#define MMA16816(c0, c1, c2, c3, a0, a1, a2, a3, b0, b1) \
    asm volatile("mma.sync.aligned.m16n8k16.row.col.f32.f16.f16.f32 " \
        "{%0,%1,%2,%3}, {%4,%5,%6,%7}, {%8,%9}, {%0,%1,%2,%3};" \
        : "+f"(c0), "+f"(c1), "+f"(c2), "+f"(c3) \
        : "r"(a0), "r"(a1), "r"(a2), "r"(a3), "r"(b0), "r"(b1))

#define CP_A16(dst, srcp) \
    asm volatile("cp.async.cg.shared.global [%0], [%1], 16;" \
        :: "r"(dst), "l"(__cvta_generic_to_global(srcp)) : "memory")
#define CP_COMMIT() asm volatile("cp.async.commit_group;" ::: "memory")

// ---------------------------------------------------------------------------
// K1: MERGED prep+embed kernel. grid 4992:
//   blocks [0,4096):       embed (4 tokens/block) -> h1 hi/lo
//   blocks [4096,4672):    cat_W transpose+split (576 = 72 x 8 features)
//   blocks [4672,4992):    model_W^T (256) + [fcu|fco]^T (64)
// ---------------------------------------------------------------------------
__global__ void __launch_bounds__(256)
k_prep_embed(const float* __restrict__ x, const float* __restrict__ embs,
             const float* __restrict__ feat_W, const float* __restrict__ feat_b,
             const float* __restrict__ catW, const float* __restrict__ Wm,
             const float* __restrict__ fcuW, const float* __restrict__ fcoW) {
    __shared__ float sm[32][65];        // catw tile; embed overlays 4x32
    int b = blockIdx.x;
    int tid = threadIdx.x;

    if (b < 4096) {
        // ---- embed ----
        int bt0 = b * 4;
        float* sx = &sm[0][0];          // [4][32] overlay
        if (tid < 128) {
            int t = tid >> 5, j = tid & 31;
            sx[t * 32 + j] = x[(bt0 + t) * 32 + j];
        }
        __syncthreads();

        int c = tid;
        float fw[NCONT];
#pragma unroll
        for (int j = 0; j < NCONT; j++) fw[j] = feat_W[j * HDIM + c];
        float fb = feat_b[c];

#pragma unroll
        for (int t = 0; t < 4; t++) {
            float e = 0.f;
#pragma unroll
            for (int f = 0; f < NCAT; f++) {
                int id = (int)sx[t * 32 + f] + 1;
                e += embs[((size_t)f * VPAD + id) * HDIM + c];
            }
            float acc = fb + e * 0.125f;
#pragma unroll
            for (int j = 0; j < NCONT; j++)
                acc += sx[t * 32 + NCAT + j] * fw[j];
            __half hi = __float2half_rn(acc);
            __half lo = __float2half_rn(acc - __half2float(hi));
            g_h1h[(size_t)(bt0 + t) * HDIM + c] = hi;
            g_h1l[(size_t)(bt0 + t) * HDIM + c] = lo;
        }
    } else if (b < 4672) {
        // ---- cat_W transpose+split ----
        int idx = b - 4096;
        int f   = idx / 72;
        int sub = idx - f * 72;
        int k0 = (sub % 8) * 32;
        int n0 = (sub / 8) * 64;

        int n_local = tid & 63;
        int k_local = tid >> 6;          // 0..3
#pragma unroll
        for (int p = 0; p < 8; p++) {
            int k = k_local + p * 4;
            int n = n0 + n_local;
            sm[k][n_local] = (n < VPAD)
                ? catW[((size_t)f * HDIM + k0 + k) * VPAD + n] : 0.f;
        }
        __syncthreads();

        int k2 = tid & 31;
        int nl = tid >> 5;               // 0..7
#pragma unroll
        for (int p = 0; p < 8; p++) {
            int n = nl + p * 8;
            float v = sm[k2][n];
            __half hi = __float2half_rn(v);
            __half lo = __float2half_rn(v - __half2float(hi));
            size_t o = ((size_t)f * NPAD + n0 + n) * HDIM + k0 + k2;
            g_cwh[o] = hi;
            g_cwl[o] = lo;
        }
    } else {
        // ---- small preps ----
        int j = b - 4672;                // 0..319
        int k = tid;
        if (j < HDIM) {
            float v = Wm[k * HDIM + j];
            __half hi = __float2half_rn(v);
            __half lo = __float2half_rn(v - __half2float(hi));
            g_mwh[j * HDIM + k] = hi;
            g_mwl[j * HDIM + k] = lo;
        } else {
            int jj = j - HDIM;           // 0..63
            float v = (jj < 32) ? fcuW[k * ODIM + jj] : fcoW[k * ODIM + (jj - 32)];
            __half hi = __float2half_rn(v);
            __half lo = __float2half_rn(v - __half2float(hi));
            g_fwh[jj * HDIM + k] = hi;
            g_fwl[jj * HDIM + k] = lo;
        }
    }
}

// ---------------------------------------------------------------------------
// Double-buffered smem layout (K-chunk 64, pitch 72)
// ---------------------------------------------------------------------------
#define APITCH 72
#define BUF_SZ 55296
#define O_AL   18432
#define O_BH   36864
#define O_BL   46080
#define S_CAT2 (2 * BUF_SZ)             // 110592
#define SMEM_DB (S_CAT2 + 256)          // 110848
// stage (float[128][65] = 33280 B) reuses buffer0 after the MMA loop

// ---------------------------------------------------------------------------
// HMMA core 128x64, cp.async double-buffered, 4 chunks of K=64 (256 threads)
// ---------------------------------------------------------------------------
__device__ __forceinline__ void hmma_tile_db(
    uint32_t sbase, int tid, int wid, int lane,
    const __half* __restrict__ Ah, const __half* __restrict__ Al, int m0,
    const __half* __restrict__ Bh0, const __half* __restrict__ Bl0,
    float acc[2][4][4])
{
    const int rw = (wid & 3) * 32;
    const int cw = (wid >> 2) * 32;
    uint32_t a_row = (uint32_t)(lane & 15);
    uint32_t a_c8  = (uint32_t)((lane >> 4) * 8);
    uint32_t b_row = (uint32_t)((lane & 7) + ((lane >> 3) & 1) * 8);
    uint32_t b_c8  = (uint32_t)((lane >> 4) * 8);

    auto issue = [&](int buf, int kc) {
        uint32_t base = sbase + buf * BUF_SZ;
#pragma unroll
        for (int i = 0; i < 4; i++) {
            int id = tid + i * 256;
            int r  = id >> 3;
            int c8 = (id & 7) * 8;
            size_t src = (size_t)(m0 + r) * HDIM + kc + c8;
            uint32_t off = (uint32_t)((r * APITCH + c8) * 2);
            CP_A16(base + off,        Ah + src);
            CP_A16(base + O_AL + off, Al + src);
        }
#pragma unroll
        for (int i = 0; i < 2; i++) {
            int id = tid + i * 256;
            int r  = id >> 3;
            int c8 = (id & 7) * 8;
            size_t src = (size_t)r * HDIM + kc + c8;
            uint32_t off = (uint32_t)((r * APITCH + c8) * 2);
            CP_A16(base + O_BH + off, Bh0 + src);
            CP_A16(base + O_BL + off, Bl0 + src);
        }
        CP_COMMIT();
    };

    issue(0, 0);
    int cur = 0;
#pragma unroll
    for (int ki = 0; ki < 4; ki++) {
        if (ki < 3) {
            issue(cur ^ 1, (ki + 1) * 64);
            asm volatile("cp.async.wait_group 1;" ::: "memory");
        } else {
            asm volatile("cp.async.wait_group 0;" ::: "memory");
        }
        __syncthreads();

        uint32_t bA  = sbase + cur * BUF_SZ;
        uint32_t bAl = bA + O_AL;
        uint32_t bBh = bA + O_BH;
        uint32_t bBl = bA + O_BL;
#pragma unroll
        for (int ks = 0; ks < 4; ks++) {
            int kk = ks * 16;
            uint32_t ah[2][4], al[2][4];
#pragma unroll
            for (int mf = 0; mf < 2; mf++) {
                uint32_t off = ((rw + mf * 16 + a_row) * APITCH + kk + a_c8) * 2;
                LDSM_X4(ah[mf][0], ah[mf][1], ah[mf][2], ah[mf][3], bA  + off);
                LDSM_X4(al[mf][0], al[mf][1], al[mf][2], al[mf][3], bAl + off);
            }
            uint32_t bh[4][2], bl[4][2];
#pragma unroll
            for (int g = 0; g < 2; g++) {
                uint32_t off = ((cw + g * 16 + b_row) * APITCH + kk + b_c8) * 2;
                uint32_t r0, r1, r2, r3;
                LDSM_X4(r0, r1, r2, r3, bBh + off);
                bh[g * 2 + 0][0] = r0; bh[g * 2 + 0][1] = r2;
                bh[g * 2 + 1][0] = r1; bh[g * 2 + 1][1] = r3;
                LDSM_X4(r0, r1, r2, r3, bBl + off);
                bl[g * 2 + 0][0] = r0; bl[g * 2 + 0][1] = r2;
                bl[g * 2 + 1][0] = r1; bl[g * 2 + 1][1] = r3;
            }
#pragma unroll
            for (int mf = 0; mf < 2; mf++)
#pragma unroll
                for (int nf = 0; nf < 4; nf++) {
                    MMA16816(acc[mf][nf][0], acc[mf][nf][1], acc[mf][nf][2], acc[mf][nf][3],
                             ah[mf][0], ah[mf][1], ah[mf][2], ah[mf][3],
                             bh[nf][0], bh[nf][1]);
                    MMA16816(acc[mf][nf][0], acc[mf][nf][1], acc[mf][nf][2], acc[mf][nf][3],
                             ah[mf][0], ah[mf][1], ah[mf][2], ah[mf][3],
                             bl[nf][0], bl[nf][1]);
                    MMA16816(acc[mf][nf][0], acc[mf][nf][1], acc[mf][nf][2], acc[mf][nf][3],
                             al[mf][0], al[mf][1], al[mf][2], al[mf][3],
                             bh[nf][0], bh[nf][1]);
                }
        }
        __syncthreads();
        cur ^= 1;
    }
}

// ---------------------------------------------------------------------------
// K2: h = h1 @ model_W + model_b via HMMA; emits h hi/lo. grid (128,4).
// ---------------------------------------------------------------------------
__global__ void __launch_bounds__(256)
k_gemmh_mm(const float* __restrict__ bm) {
    extern __shared__ char smem[];
    uint32_t sbase = smem_u32(smem);
    int tid = threadIdx.x, wid = tid >> 5, lane = tid & 31;
    int m0 = blockIdx.x * 128;
    int n0 = blockIdx.y * 64;

    float* scat = (float*)(smem + S_CAT2);
    if (tid < 64) scat[tid] = bm[n0 + tid];

    float acc[2][4][4];
#pragma unroll
    for (int mf = 0; mf < 2; mf++)
#pragma unroll
        for (int nf = 0; nf < 4; nf++)
#pragma unroll
            for (int q = 0; q < 4; q++) acc[mf][nf][q] = 0.f;

    hmma_tile_db(sbase, tid, wid, lane,
                 g_h1h, g_h1l, m0,
                 g_mwh + (size_t)n0 * HDIM, g_mwl + (size_t)n0 * HDIM, acc);

    float* stage = (float*)smem;
    const int rw = (wid & 3) * 32;
    const int cw = (wid >> 2) * 32;
    int qr = lane >> 2;
    int qc = (lane & 3) * 2;
#pragma unroll
    for (int mf = 0; mf < 2; mf++)
#pragma unroll
        for (int nf = 0; nf < 4; nf++) {
            int col = cw + nf * 8 + qc;
            int r1 = rw + mf * 16 + qr;
            int r2 = r1 + 8;
            stage[r1 * 65 + col]     = acc[mf][nf][0] + scat[col];
            stage[r1 * 65 + col + 1] = acc[mf][nf][1] + scat[col + 1];
            stage[r2 * 65 + col]     = acc[mf][nf][2] + scat[col];
            stage[r2 * 65 + col + 1] = acc[mf][nf][3] + scat[col + 1];
        }
    __syncthreads();

#pragma unroll
    for (int i = 0; i < 32; i++) {
        int e = tid + i * 256;
        int r = e >> 6;
        int col = e & 63;
        float v = stage[r * 65 + col];
        size_t o = (size_t)(m0 + r) * HDIM + n0 + col;
        __half hi = __float2half_rn(v);
        g_hh[o] = hi;
        g_hl[o] = __float2half_rn(v - __half2float(hi));
    }
}

// ---------------------------------------------------------------------------
// K3: MERGED heads + extra kernel. grid 640:
//   blocks [0,128):    heads HMMA (m0 = b*128)
//   blocks [128,640):  "+1" columns (row0 = (b-128)*32); initializes g_amax
// ---------------------------------------------------------------------------
__global__ void __launch_bounds__(256)
k_heads_extra(const float* __restrict__ fcub, const float* __restrict__ fcob,
              const float* __restrict__ catW, const float* __restrict__ catb,
              float* __restrict__ out) {
    extern __shared__ char smem[];
    int b = blockIdx.x;
    int tid = threadIdx.x;

    if (b < 128) {
        // ---- heads ----
        uint32_t sbase = smem_u32(smem);
        int wid = tid >> 5, lane = tid & 31;
        int m0 = b * 128;

        float acc[2][4][4];
#pragma unroll
        for (int mf = 0; mf < 2; mf++)
#pragma unroll
            for (int nf = 0; nf < 4; nf++)
#pragma unroll
                for (int q = 0; q < 4; q++) acc[mf][nf][q] = 0.f;

        hmma_tile_db(sbase, tid, wid, lane,
                     g_hh, g_hl, m0, g_fwh, g_fwl, acc);

        const int rw = (wid & 3) * 32;
        const int cw = (wid >> 2) * 32;
        int qr = lane >> 2;
        int qc = (lane & 3) * 2;
#pragma unroll
        for (int mf = 0; mf < 2; mf++)
#pragma unroll
            for (int nf = 0; nf < 4; nf++) {
                int col = cw + nf * 8 + qc;
                int r1 = m0 + rw + mf * 16 + qr;
                int r2 = r1 + 8;
#pragma unroll
                for (int e = 0; e < 2; e++) {
                    int gc = col + e;
                    float bia = (gc < 32) ? fcub[gc] : fcob[gc - 32];
                    float v1 = acc[mf][nf][e]     + bia;
                    float v2 = acc[mf][nf][2 + e] + bia;
                    if (gc < 32) {
                        if (gc >= NCAT) {
                            out[r1 * ODIM + gc] = v1;
                            out[r2 * ODIM + gc] = v2;
                        }
                    } else {
                        out[OFF_O + r1 * ODIM + (gc - 32)] = v1;
                        out[OFF_O + r2 * ODIM + (gc - 32)] = v2;
                    }
                }
            }
    } else {
        // ---- extra: the 8 "+1" columns; plain-store initializes g_amax ----
        int row0 = (b - 128) * 32;
        float* sW = (float*)smem;                    // [8][257]
        float* sh = (float*)(smem + 8 * 257 * 4);    // [32][257]

#pragma unroll
        for (int i = 0; i < 8; i++) {
            int id = tid + i * 256;
            int f = id >> 8;
            int k = id & 255;
            sW[f * 257 + k] = catW[((size_t)f * HDIM + k) * VPAD + c_colf[f]];
        }
#pragma unroll
        for (int i = 0; i < 32; i++) {
            int id = tid + i * 256;
            int r = id >> 8;
            int k = id & 255;
            size_t o = (size_t)(row0 + r) * HDIM + k;
            sh[r * 257 + k] = __half2float(g_hh[o]) + __half2float(g_hl[o]);
        }
        __syncthreads();

        int f = tid & 7;
        int r = tid >> 3;
        int col = c_colf[f];
        float s = catb[f * VPAD + col];
#pragma unroll 8
        for (int k = 0; k < HDIM; k++) s += sh[r * 257 + k] * sW[f * 257 + k];

        out[OFF_C + ((size_t)f * BT + row0 + r) * VPAD + col] = s;

        unsigned u = __float_as_uint(s);
        unsigned key = (u & 0x80000000u) ? ~u : (u | 0x80000000u);
        unsigned long long pk =
            ((unsigned long long)key << 32) | (unsigned long long)(1023 - col);
        g_amax[(size_t)f * BT + row0 + r] = pk;
    }
}

// ---------------------------------------------------------------------------
// K4: HMMA logits, 30 FULL tiles. grid (128, 30), 256 thr.
// Fragment argmax + c write + fused -1e30 fill chunks.
// ---------------------------------------------------------------------------
__global__ void __launch_bounds__(256)
k_logits_mm(const float* __restrict__ catb, float* __restrict__ out) {
    extern __shared__ char smem[];
    uint32_t sbase = smem_u32(smem);
    int tid = threadIdx.x, wid = tid >> 5, lane = tid & 31;
    int ti = blockIdx.y;
    int f  = c_tf2[ti];
    int n0 = c_tn2[ti];
    int m0 = blockIdx.x * 128;

    float* scat = (float*)(smem + S_CAT2);
    if (tid < 64) scat[tid] = catb[f * VPAD + n0 + tid];

    float acc[2][4][4];
#pragma unroll
    for (int mf = 0; mf < 2; mf++)
#pragma unroll
        for (int nf = 0; nf < 4; nf++)
#pragma unroll
            for (int q = 0; q < 4; q++) acc[mf][nf][q] = 0.f;

    hmma_tile_db(sbase, tid, wid, lane,
                 g_hh, g_hl, m0,
                 g_cwh + ((size_t)f * NPAD + n0) * HDIM,
                 g_cwl + ((size_t)f * NPAD + n0) * HDIM, acc);

    float* stage = (float*)smem;
    const int rw = (wid & 3) * 32;
    const int cw = (wid >> 2) * 32;
    int qr = lane >> 2;
    int qc = (lane & 3) * 2;

    unsigned long long best1[2], best2[2];
#pragma unroll
    for (int mf = 0; mf < 2; mf++) { best1[mf] = 0ULL; best2[mf] = 0ULL; }

#pragma unroll
    for (int mf = 0; mf < 2; mf++)
#pragma unroll
        for (int nf = 0; nf < 4; nf++) {
            int col = cw + nf * 8 + qc;
            int r1 = rw + mf * 16 + qr;
            int r2 = r1 + 8;
            float v00 = acc[mf][nf][0] + scat[col];
            float v01 = acc[mf][nf][1] + scat[col + 1];
            float v10 = acc[mf][nf][2] + scat[col];
            float v11 = acc[mf][nf][3] + scat[col + 1];
            stage[r1 * 65 + col]     = v00;
            stage[r1 * 65 + col + 1] = v01;
            stage[r2 * 65 + col]     = v10;
            stage[r2 * 65 + col + 1] = v11;
#pragma unroll
            for (int e = 0; e < 2; e++) {
                float va = e ? v01 : v00;
                float vb = e ? v11 : v10;
                int gc = n0 + col + e;
                unsigned ua = __float_as_uint(va);
                unsigned ka = (ua & 0x80000000u) ? ~ua : (ua | 0x80000000u);
                unsigned long long pa =
                    ((unsigned long long)ka << 32) | (unsigned long long)(1023 - gc);
                if (pa > best1[mf]) best1[mf] = pa;
                unsigned ub = __float_as_uint(vb);
                unsigned kb = (ub & 0x80000000u) ? ~ub : (ub | 0x80000000u);
                unsigned long long pb =
                    ((unsigned long long)kb << 32) | (unsigned long long)(1023 - gc);
                if (pb > best2[mf]) best2[mf] = pb;
            }
        }
#pragma unroll
    for (int mf = 0; mf < 2; mf++) {
#pragma unroll
        for (int d = 1; d < 4; d <<= 1) {
            unsigned long long o1 = __shfl_xor_sync(0xFFFFFFFFu, best1[mf], d);
            unsigned long long o2 = __shfl_xor_sync(0xFFFFFFFFu, best2[mf], d);
            if (o1 > best1[mf]) best1[mf] = o1;
            if (o2 > best2[mf]) best2[mf] = o2;
        }
        if ((lane & 3) == 0) {
            int r1 = rw + mf * 16 + qr;
            atomicMax(&g_amax[(size_t)f * BT + m0 + r1], best1[mf]);
            atomicMax(&g_amax[(size_t)f * BT + m0 + r1 + 8], best2[mf]);
        }
    }
    __syncthreads();

    float* cbase = out + OFF_C + (size_t)f * BT * VPAD;
#pragma unroll
    for (int i = 0; i < 32; i++) {
        int e = tid + i * 256;
        int r = e >> 6;
        int col = e & 63;
        cbase[(size_t)(m0 + r) * VPAD + n0 + col] = stage[r * 65 + col];
    }

    // Fused -1e30 fill chunks (hidden behind compute across the grid)
    for (int cidx = ti; cidx < 34; cidx += 30) {
        int ff = c_ff[cidx];
        int c0 = c_fc0[cidx];
        float* fb = out + OFF_C + (size_t)ff * BT * VPAD;
#pragma unroll
        for (int i = 0; i < 32; i++) {
            int e = tid + i * 256;
            int r = e >> 6;
            int col = e & 63;
            fb[(size_t)(m0 + r) * VPAD + c0 + col] = NEGINF;
        }
    }
}

// ---------------------------------------------------------------------------
// K5: decode argmax into u[:, :, 0:8]
// ---------------------------------------------------------------------------
__global__ void k_writearg(float* __restrict__ out) {
    int i = blockIdx.x * blockDim.x + threadIdx.x;
    if (i >= NCAT * BT) return;
    int f  = i / BT;
    int bt = i - f * BT;
    unsigned long long p = g_amax[i];
    int idx = 1023 - (int)(p & 0xFFFFFFFFu);
    out[bt * ODIM + f] = (float)idx - 1.0f;
}

// ---------------------------------------------------------------------------
extern "C" void kernel_launch(void* const* d_in, const int* in_sizes, int n_in,
                              void* d_out, int out_size) {
    const float* x       = (const float*)d_in[0];
    const float* embs    = (const float*)d_in[1];
    const float* feat_W  = (const float*)d_in[2];
    const float* feat_b  = (const float*)d_in[3];
    const float* model_W = (const float*)d_in[4];
    const float* model_b = (const float*)d_in[5];
    const float* fcu_W   = (const float*)d_in[6];
    const float* fcu_b   = (const float*)d_in[7];
    const float* fco_W   = (const float*)d_in[8];
    const float* fco_b   = (const float*)d_in[9];
    const float* cat_W   = (const float*)d_in[10];
    const float* cat_b   = (const float*)d_in[11];
    float* out = (float*)d_out;

    cudaFuncSetAttribute(k_logits_mm, cudaFuncAttributeMaxDynamicSharedMemorySize, SMEM_DB);
    cudaFuncSetAttribute(k_heads_extra, cudaFuncAttributeMaxDynamicSharedMemorySize, SMEM_DB);
    cudaFuncSetAttribute(k_gemmh_mm, cudaFuncAttributeMaxDynamicSharedMemorySize, SMEM_DB);

    k_prep_embed<<<4992, 256>>>(x, embs, feat_W, feat_b, cat_W,
                                model_W, fcu_W, fco_W);
    k_gemmh_mm<<<dim3(BT / 128, 4), 256, SMEM_DB>>>(model_b);
    k_heads_extra<<<640, 256, SMEM_DB>>>(fcu_b, fco_b, cat_W, cat_b, out);
    k_logits_mm<<<dim3(BT / 128, 30), 256, SMEM_DB>>>(cat_b, out);
    k_writearg<<<(NCAT * BT + 255) / 256, 256>>>(out);
}